// round 1
// baseline (speedup 1.0000x reference)
#include <cuda_runtime.h>

// SSIM fused kernel for (32, 3, 512, 512) fp32 images, 11x11 Gaussian (sigma=1.5).
// Separable convolution, fully fused: load tile -> horizontal blur of 5 fields
// -> vertical blur -> SSIM map -> block partial sum. Deterministic 2-stage reduce.

#define TW 32
#define TH 32
#define IW 42      // TW + 10
#define IH 42      // TH + 10
#define SP 48      // padded smem pitch (floats)
#define PLANES 96  // 32 batch * 3 channels
#define GX 16
#define GY 16
#define NBLK (GX * GY * PLANES)
#define NPIX 25165824.0   // 32*3*512*512

__device__ float g_partials[NBLK];

__global__ __launch_bounds__(256) void ssim_main(const float* __restrict__ img1,
                                                 const float* __restrict__ img2)
{
    // Gaussian(11, sigma=1.5), normalized; matches reference f64->f32 window.
    const float W[11] = {
        0.00102838f, 0.00759876f, 0.03600077f, 0.10936069f, 0.21300553f,
        0.26601172f,
        0.21300553f, 0.10936069f, 0.03600077f, 0.00759876f, 0.00102838f
    };

    __shared__ __align__(16) float sa[IH][SP];
    __shared__ __align__(16) float sb[IH][SP];
    __shared__ __align__(16) float hb[5][IH][TW];
    __shared__ float warpsum[8];

    const int tid = threadIdx.x;
    const int plane = blockIdx.z;
    const int x0 = blockIdx.x * TW;
    const int y0 = blockIdx.y * TH;
    const float* p1 = img1 + (size_t)plane * (512 * 512);
    const float* p2 = img2 + (size_t)plane * (512 * 512);

    // ---- Phase 1: cooperative halo load with zero padding ----
    #pragma unroll
    for (int i = 0; i < 7; i++) {
        int idx = tid + i * 256;
        if (idx < IH * IW) {
            int r = idx / IW;
            int c = idx - r * IW;
            int gy = y0 + r - 5;
            int gx = x0 + c - 5;
            float a = 0.f, b = 0.f;
            if ((unsigned)gy < 512u && (unsigned)gx < 512u) {
                a = p1[gy * 512 + gx];
                b = p2[gy * 512 + gx];
            }
            sa[r][c] = a;
            sb[r][c] = b;
        }
    }
    __syncthreads();

    // ---- Phase 2: horizontal pass, 4 outputs per task, 5 fields ----
    // Tasks: 42 rows * 8 x-quads = 336.
    #pragma unroll
    for (int it = 0; it < 2; it++) {
        int t = tid + it * 256;
        if (t < IH * 8) {
            int r = t >> 3;
            int xq = (t & 7) << 2;

            float a[16], b[16];
            #pragma unroll
            for (int j = 0; j < 4; j++) {
                float4 av4 = *reinterpret_cast<const float4*>(&sa[r][xq + 4 * j]);
                float4 bv4 = *reinterpret_cast<const float4*>(&sb[r][xq + 4 * j]);
                a[4 * j + 0] = av4.x; a[4 * j + 1] = av4.y; a[4 * j + 2] = av4.z; a[4 * j + 3] = av4.w;
                b[4 * j + 0] = bv4.x; b[4 * j + 1] = bv4.y; b[4 * j + 2] = bv4.z; b[4 * j + 3] = bv4.w;
            }

            float o0[4], o1[4], o2[4], o3[4], o4[4];
            #pragma unroll
            for (int j = 0; j < 4; j++) { o0[j] = 0.f; o1[j] = 0.f; o2[j] = 0.f; o3[j] = 0.f; o4[j] = 0.f; }

            #pragma unroll
            for (int j = 0; j < 4; j++) {
                #pragma unroll
                for (int k = 0; k < 11; k++) {
                    float av = a[j + k];
                    float bv = b[j + k];
                    o0[j] += W[k] * av;
                    o1[j] += W[k] * bv;
                    o2[j] += W[k] * (av * av);
                    o3[j] += W[k] * (bv * bv);
                    o4[j] += W[k] * (av * bv);
                }
            }

            float4 v;
            v.x = o0[0]; v.y = o0[1]; v.z = o0[2]; v.w = o0[3];
            *reinterpret_cast<float4*>(&hb[0][r][xq]) = v;
            v.x = o1[0]; v.y = o1[1]; v.z = o1[2]; v.w = o1[3];
            *reinterpret_cast<float4*>(&hb[1][r][xq]) = v;
            v.x = o2[0]; v.y = o2[1]; v.z = o2[2]; v.w = o2[3];
            *reinterpret_cast<float4*>(&hb[2][r][xq]) = v;
            v.x = o3[0]; v.y = o3[1]; v.z = o3[2]; v.w = o3[3];
            *reinterpret_cast<float4*>(&hb[3][r][xq]) = v;
            v.x = o4[0]; v.y = o4[1]; v.z = o4[2]; v.w = o4[3];
            *reinterpret_cast<float4*>(&hb[4][r][xq]) = v;
        }
    }
    __syncthreads();

    // ---- Phase 3: vertical pass, 4 outputs per thread, + SSIM + reduce ----
    const int vx = tid & 31;
    const int vyb = (tid >> 5) << 2;   // 8 groups of 4 rows = 32 rows

    float v0[4], v1[4], v2[4], v3[4], v4[4];
    #pragma unroll
    for (int j = 0; j < 4; j++) { v0[j] = 0.f; v1[j] = 0.f; v2[j] = 0.f; v3[j] = 0.f; v4[j] = 0.f; }

    #pragma unroll
    for (int k = 0; k < 14; k++) {
        float c0 = hb[0][vyb + k][vx];
        float c1 = hb[1][vyb + k][vx];
        float c2 = hb[2][vyb + k][vx];
        float c3 = hb[3][vyb + k][vx];
        float c4 = hb[4][vyb + k][vx];
        #pragma unroll
        for (int j = 0; j < 4; j++) {
            int kk = k - j;
            if (kk >= 0 && kk < 11) {
                float w = W[kk];
                v0[j] += w * c0;
                v1[j] += w * c1;
                v2[j] += w * c2;
                v3[j] += w * c3;
                v4[j] += w * c4;
            }
        }
    }

    float acc = 0.f;
    #pragma unroll
    for (int j = 0; j < 4; j++) {
        float mu1 = v0[j], mu2 = v1[j];
        float mu1s = mu1 * mu1;
        float mu2s = mu2 * mu2;
        float mu12 = mu1 * mu2;
        float s1  = v2[j] - mu1s;
        float s2  = v3[j] - mu2s;
        float s12 = v4[j] - mu12;
        float num = (2.f * mu12 + 1e-4f) * (2.f * s12 + 9e-4f);
        float den = (mu1s + mu2s + 1e-4f) * (s1 + s2 + 9e-4f);
        acc += num / den;
    }

    // block reduce (8 warps)
    acc += __shfl_down_sync(0xffffffffu, acc, 16);
    acc += __shfl_down_sync(0xffffffffu, acc, 8);
    acc += __shfl_down_sync(0xffffffffu, acc, 4);
    acc += __shfl_down_sync(0xffffffffu, acc, 2);
    acc += __shfl_down_sync(0xffffffffu, acc, 1);
    if ((tid & 31) == 0) warpsum[tid >> 5] = acc;
    __syncthreads();
    if (tid < 8) {
        float s = warpsum[tid];
        s += __shfl_down_sync(0xffu, s, 4);
        s += __shfl_down_sync(0xffu, s, 2);
        s += __shfl_down_sync(0xffu, s, 1);
        if (tid == 0) {
            int bid = (blockIdx.z * GY + blockIdx.y) * GX + blockIdx.x;
            g_partials[bid] = s;
        }
    }
}

// Deterministic second-stage reduction (double accumulate, fixed order).
__global__ void ssim_reduce(float* __restrict__ out)
{
    __shared__ double sd[1024];
    double s = 0.0;
    for (int i = threadIdx.x; i < NBLK; i += 1024) {
        s += (double)g_partials[i];
    }
    sd[threadIdx.x] = s;
    __syncthreads();
    #pragma unroll
    for (int off = 512; off > 0; off >>= 1) {
        if (threadIdx.x < (unsigned)off) sd[threadIdx.x] += sd[threadIdx.x + off];
        __syncthreads();
    }
    if (threadIdx.x == 0) out[0] = (float)(sd[0] * (1.0 / NPIX));
}

extern "C" void kernel_launch(void* const* d_in, const int* in_sizes, int n_in,
                              void* d_out, int out_size)
{
    const float* img1 = (const float*)d_in[0];
    const float* img2 = (const float*)d_in[1];
    // d_in[2] is the Gaussian window; its values are baked in as immediates.
    (void)in_sizes; (void)n_in; (void)out_size;

    dim3 grid(GX, GY, PLANES);
    ssim_main<<<grid, 256>>>(img1, img2);
    ssim_reduce<<<1, 1024>>>((float*)d_out);
}

// round 2
// speedup vs baseline: 1.0030x; 1.0030x over previous
#include <cuda_runtime.h>

// SSIM fused kernel, packed-f32x2 edition.
// (32,3,512,512) fp32, 11x11 Gaussian sigma=1.5, separable, fully fused.
// Pairing scheme:
//   lane pair (img1, img2): mu1/mu2 convolved together; E[a^2]/E[b^2] together
//   lane pair (out j, out j+1): E[ab] convolved with shifted-element pairs
// Deterministic 2-stage reduction.

#define TW 32
#define TH 32
#define IW 42      // TW + 10
#define IH 42      // TH + 10
#define SPP 43     // sab pitch in u64 (odd -> break bank alignment)
#define PLANES 96  // 32 batch * 3 channels
#define GX 16
#define GY 16
#define NBLK (GX * GY * PLANES)
#define NPIX 25165824.0   // 32*3*512*512

typedef unsigned long long u64;

__device__ __forceinline__ u64 pk2(float lo, float hi) {
    u64 r; asm("mov.b64 %0,{%1,%2};" : "=l"(r) : "f"(lo), "f"(hi)); return r;
}
__device__ __forceinline__ void upk(u64 v, float& lo, float& hi) {
    asm("mov.b64 {%0,%1},%2;" : "=f"(lo), "=f"(hi) : "l"(v));
}
__device__ __forceinline__ u64 ffma2(u64 a, u64 b, u64 c) {
    u64 d; asm("fma.rn.f32x2 %0,%1,%2,%3;" : "=l"(d) : "l"(a), "l"(b), "l"(c)); return d;
}
__device__ __forceinline__ u64 fmul2(u64 a, u64 b) {
    u64 d; asm("mul.rn.f32x2 %0,%1,%2;" : "=l"(d) : "l"(a), "l"(b)); return d;
}

__device__ float g_partials[NBLK];

__global__ __launch_bounds__(256) void ssim_main(const float* __restrict__ img1,
                                                 const float* __restrict__ img2)
{
    // Gaussian(11, sigma=1.5), normalized (f64-derived, matches reference).
    const float WS[11] = {
        0.00102838f, 0.00759876f, 0.03600077f, 0.10936069f, 0.21300553f,
        0.26601172f,
        0.21300553f, 0.10936069f, 0.03600077f, 0.00759876f, 0.00102838f
    };
    u64 ww[11];
    #pragma unroll
    for (int k = 0; k < 11; k++) ww[k] = pk2(WS[k], WS[k]);

    __shared__ __align__(16) u64 sab[IH][SPP];     // interleaved (a,b) pairs
    __shared__ __align__(16) u64 hb01[IH][TW];     // packed (mu1_h, mu2_h)
    __shared__ __align__(16) u64 hb23[IH][TW];     // packed (Ea2_h, Eb2_h)
    __shared__ __align__(16) float hb4[IH][TW];    // Eab_h scalar
    __shared__ float warpsum[8];

    const int tid = threadIdx.x;
    const int plane = blockIdx.z;
    const int x0 = blockIdx.x * TW;
    const int y0 = blockIdx.y * TH;
    const float* p1 = img1 + (size_t)plane * (512 * 512);
    const float* p2 = img2 + (size_t)plane * (512 * 512);

    // ---- Phase 1: cooperative halo load, interleave (a,b) ----
    #pragma unroll
    for (int i = 0; i < 7; i++) {
        int idx = tid + i * 256;
        if (idx < IH * IW) {
            int r = idx / IW;
            int c = idx - r * IW;
            int gy = y0 + r - 5;
            int gx = x0 + c - 5;
            float a = 0.f, b = 0.f;
            if ((unsigned)gy < 512u && (unsigned)gx < 512u) {
                a = p1[gy * 512 + gx];
                b = p2[gy * 512 + gx];
            }
            sab[r][c] = pk2(a, b);
        }
    }
    __syncthreads();

    // ---- Phase 2: horizontal pass, 4 outputs per task, packed ----
    // 336 tasks = 42 rows * 8 x-quads
    #pragma unroll
    for (int it = 0; it < 2; it++) {
        int t = tid + it * 256;
        if (t < IH * 8) {
            int r = t >> 3;
            int xq = (t & 7) << 2;

            u64 o01[4] = {0, 0, 0, 0};
            u64 o23[4] = {0, 0, 0, 0};
            u64 o4p0 = 0, o4p1 = 0;
            float abprev = 0.f;

            #pragma unroll
            for (int i = 0; i < 14; i++) {
                u64 e = sab[r][xq + i];           // (a_i, b_i)
                u64 esq = fmul2(e, e);            // (a_i^2, b_i^2)
                float fa, fb;
                upk(e, fa, fb);
                float ab = fa * fb;

                #pragma unroll
                for (int j = 0; j < 4; j++) {
                    int k = i - j;
                    if (k >= 0 && k < 11) {
                        o01[j] = ffma2(e,   ww[k], o01[j]);
                        o23[j] = ffma2(esq, ww[k], o23[j]);
                    }
                }
                if (i >= 1) {
                    u64 ap = pk2(abprev, ab);     // (ab[i-1], ab[i])
                    int k0 = i - 1;               // -> outputs (0,1)
                    if (k0 < 11) o4p0 = ffma2(ap, ww[k0], o4p0);
                    int k1 = i - 3;               // -> outputs (2,3)
                    if (k1 >= 0 && k1 < 11) o4p1 = ffma2(ap, ww[k1], o4p1);
                }
                abprev = ab;
            }

            *reinterpret_cast<ulonglong2*>(&hb01[r][xq])     = make_ulonglong2(o01[0], o01[1]);
            *reinterpret_cast<ulonglong2*>(&hb01[r][xq + 2]) = make_ulonglong2(o01[2], o01[3]);
            *reinterpret_cast<ulonglong2*>(&hb23[r][xq])     = make_ulonglong2(o23[0], o23[1]);
            *reinterpret_cast<ulonglong2*>(&hb23[r][xq + 2]) = make_ulonglong2(o23[2], o23[3]);
            float s0, s1, s2, s3;
            upk(o4p0, s0, s1);
            upk(o4p1, s2, s3);
            *reinterpret_cast<float4*>(&hb4[r][xq]) = make_float4(s0, s1, s2, s3);
        }
    }
    __syncthreads();

    // ---- Phase 3: vertical pass (packed) + SSIM + block reduce ----
    const int vx = tid & 31;
    const int vyb = (tid >> 5) << 2;   // 8 warps * 4 rows = 32 rows

    u64 v01[4] = {0, 0, 0, 0};
    u64 v23[4] = {0, 0, 0, 0};
    u64 v4p0 = 0, v4p1 = 0;
    float c4prev = 0.f;

    #pragma unroll
    for (int i = 0; i < 14; i++) {
        u64 c01 = hb01[vyb + i][vx];
        u64 c23 = hb23[vyb + i][vx];
        float c4 = hb4[vyb + i][vx];

        #pragma unroll
        for (int j = 0; j < 4; j++) {
            int k = i - j;
            if (k >= 0 && k < 11) {
                v01[j] = ffma2(c01, ww[k], v01[j]);
                v23[j] = ffma2(c23, ww[k], v23[j]);
            }
        }
        if (i >= 1) {
            u64 cp = pk2(c4prev, c4);
            int k0 = i - 1;
            if (k0 < 11) v4p0 = ffma2(cp, ww[k0], v4p0);
            int k1 = i - 3;
            if (k1 >= 0 && k1 < 11) v4p1 = ffma2(cp, ww[k1], v4p1);
        }
        c4prev = c4;
    }

    float eab[4];
    upk(v4p0, eab[0], eab[1]);
    upk(v4p1, eab[2], eab[3]);

    float acc = 0.f;
    #pragma unroll
    for (int j = 0; j < 4; j++) {
        float mu1, mu2, ea2, eb2;
        upk(v01[j], mu1, mu2);
        upk(v23[j], ea2, eb2);
        float mu1s = mu1 * mu1;
        float mu2s = mu2 * mu2;
        float mu12 = mu1 * mu2;
        float s1  = ea2 - mu1s;
        float s2  = eb2 - mu2s;
        float s12 = eab[j] - mu12;
        float num = (2.f * mu12 + 1e-4f) * (2.f * s12 + 9e-4f);
        float den = (mu1s + mu2s + 1e-4f) * (s1 + s2 + 9e-4f);
        acc += __fdividef(num, den);
    }

    // block reduce (8 warps)
    acc += __shfl_down_sync(0xffffffffu, acc, 16);
    acc += __shfl_down_sync(0xffffffffu, acc, 8);
    acc += __shfl_down_sync(0xffffffffu, acc, 4);
    acc += __shfl_down_sync(0xffffffffu, acc, 2);
    acc += __shfl_down_sync(0xffffffffu, acc, 1);
    if ((tid & 31) == 0) warpsum[tid >> 5] = acc;
    __syncthreads();
    if (tid < 8) {
        float s = warpsum[tid];
        s += __shfl_down_sync(0xffu, s, 4);
        s += __shfl_down_sync(0xffu, s, 2);
        s += __shfl_down_sync(0xffu, s, 1);
        if (tid == 0) {
            int bid = (blockIdx.z * GY + blockIdx.y) * GX + blockIdx.x;
            g_partials[bid] = s;
        }
    }
}

// Deterministic second-stage reduction: fixed-order double accumulation.
__global__ __launch_bounds__(1024) void ssim_reduce(float* __restrict__ out)
{
    __shared__ double ws[32];
    const int tid = threadIdx.x;
    const float4* p = reinterpret_cast<const float4*>(g_partials);  // 6144 vec4
    double s = 0.0;
    #pragma unroll
    for (int it = 0; it < 6; it++) {
        float4 v = p[tid + it * 1024];
        s += (double)v.x + (double)v.y + (double)v.z + (double)v.w;
    }
    #pragma unroll
    for (int off = 16; off > 0; off >>= 1)
        s += __shfl_down_sync(0xffffffffu, s, off);
    if ((tid & 31) == 0) ws[tid >> 5] = s;
    __syncthreads();
    if (tid < 32) {
        double t = ws[tid];
        #pragma unroll
        for (int off = 16; off > 0; off >>= 1)
            t += __shfl_down_sync(0xffffffffu, t, off);
        if (tid == 0) out[0] = (float)(t * (1.0 / NPIX));
    }
}

extern "C" void kernel_launch(void* const* d_in, const int* in_sizes, int n_in,
                              void* d_out, int out_size)
{
    const float* img1 = (const float*)d_in[0];
    const float* img2 = (const float*)d_in[1];
    (void)in_sizes; (void)n_in; (void)out_size;

    dim3 grid(GX, GY, PLANES);
    ssim_main<<<grid, 256>>>(img1, img2);
    ssim_reduce<<<1, 1024>>>((float*)d_out);
}